// round 10
// baseline (speedup 1.0000x reference)
#include <cuda_runtime.h>

#define B_ 256
#define C_ 2048
#define N_ 288
#define K_ 6
#define NGRP_ 32          // independent groups
#define CPB_ 8            // CTAs per batch (one per 256-column C slice)
#define CSL_ 256          // C columns per CTA slice
#define GRID_ (NGRP_ * CPB_)

typedef unsigned long long u64;

// scratch (no allocations allowed)
__device__ int g_done[B_];
__device__ float g_part[(size_t)B_ * CPB_ * 7 * N_];   // [b][slice][7][n]

__device__ __forceinline__ u64 pack2(float lo, float hi) {
    u64 p;
    asm("mov.b64 %0, {%1, %2};" : "=l"(p) : "f"(lo), "f"(hi));
    return p;
}
__device__ __forceinline__ void unpack2(u64 p, float& lo, float& hi) {
    asm("mov.b64 {%0, %1}, %2;" : "=f"(lo), "=f"(hi) : "l"(p));
}
__device__ __forceinline__ float unpack_sum(u64 p) {
    float lo, hi;
    unpack2(p, lo, hi);
    return lo + hi;
}
__device__ __forceinline__ void fma2(u64& d, u64 a, u64 b) {
    asm("fma.rn.f32x2 %0, %1, %2, %3;" : "=l"(d) : "l"(a), "l"(b), "l"(d));
}

__global__ void init_kernel() {
    if (threadIdx.x < B_) g_done[threadIdx.x] = 0;
}

// ---------------------------------------------------------------------------
// Fused persistent kernel. Group (8 CTAs) processes batches {grp, grp+32,...}.
// Per batch: phase1 partial dots (own C-slice, DRAM stream) -> flag;
// phase2 spin + redundant argmin/counts from L2-hot partials;
// phase3 scatter-mean of own C-slice, re-reading x[b] from L2.
// ---------------------------------------------------------------------------
__global__ void __launch_bounds__(N_, 2) fused_kernel(const float* __restrict__ x,
                                                      const float* __restrict__ cl,
                                                      float* __restrict__ out) {
    __shared__ float sCl[K_][CSL_];     // this CTA's cluster slice
    __shared__ float sCn[K_];
    __shared__ float sInv[K_];
    __shared__ unsigned char sAssign[N_];
    __shared__ int sCnt[K_];

    const int grp = blockIdx.x >> 3;        // 0..31
    const int j   = blockIdx.x & 7;         // slice id
    const int c0  = j * CSL_;
    const int t = threadIdx.x;              // 0..287
    const int w = t >> 5;
    const int l = t & 31;

    // one-time per CTA: stage cluster slice + full c_norm
    for (int i = t; i < K_ * CSL_; i += N_) {
        int k = i >> 8, cc = i & (CSL_ - 1);
        sCl[k][cc] = cl[k * C_ + c0 + cc];
    }
    if (w < K_) {
        float s = 0.f;
        for (int c = l; c < C_; c += 32) {
            float v = __ldg(&cl[w * C_ + c]);
            s = fmaf(v, v, s);
        }
        #pragma unroll
        for (int o = 16; o; o >>= 1) s += __shfl_xor_sync(0xffffffffu, s, o);
        if (l == 0) sCn[w] = s;
    }
    __syncthreads();

    for (int b = grp; b < B_; b += NGRP_) {
        // ================= phase 1: partial dots for slice j =================
        {
            const float* xh = x + (size_t)b * ((size_t)C_ * N_) + (size_t)c0 * N_ + t;

            u64 d2[K_];
            #pragma unroll
            for (int k = 0; k < K_; k++) d2[k] = 0ull;
            u64 xn2 = 0ull;

            float v[8], vn[8];
            #pragma unroll
            for (int u = 0; u < 8; u++) v[u] = xh[(size_t)u * N_];

            #pragma unroll 1
            for (int c = 0; c < CSL_; c += 8) {
                if (c + 8 < CSL_) {
                    #pragma unroll
                    for (int u = 0; u < 8; u++) vn[u] = xh[(size_t)(c + 8 + u) * N_];
                }
                u64 vp[4];
                #pragma unroll
                for (int u = 0; u < 4; u++) vp[u] = pack2(v[2 * u], v[2 * u + 1]);
                #pragma unroll
                for (int u = 0; u < 4; u++) fma2(xn2, vp[u], vp[u]);
                #pragma unroll
                for (int k = 0; k < K_; k++) {
                    ulonglong2 q0 = *(const ulonglong2*)&sCl[k][c];
                    ulonglong2 q1 = *(const ulonglong2*)&sCl[k][c + 4];
                    fma2(d2[k], vp[0], q0.x);
                    fma2(d2[k], vp[1], q0.y);
                    fma2(d2[k], vp[2], q1.x);
                    fma2(d2[k], vp[3], q1.y);
                }
                #pragma unroll
                for (int u = 0; u < 8; u++) v[u] = vn[u];
            }

            float* p = g_part + ((size_t)(b * CPB_ + j) * 7) * N_ + t;
            #pragma unroll
            for (int k = 0; k < K_; k++) p[k * N_] = unpack_sum(d2[k]);
            p[6 * N_] = unpack_sum(xn2);
        }

        // publish: all stores visible, then bump the batch counter
        __threadfence();
        __syncthreads();
        if (t == 0) atomicAdd(&g_done[b], 1);

        // ============ phase 2: wait for all 8 slices, argmin, counts ==========
        if (t == 0) {
            while (atomicAdd(&g_done[b], 0) < CPB_) { }
        }
        __syncthreads();
        __threadfence();

        {
            float dot[K_];
            #pragma unroll
            for (int k = 0; k < K_; k++) dot[k] = 0.f;
            float xn = 0.f;
            #pragma unroll 1
            for (int jj = 0; jj < CPB_; jj++) {
                const float* p = g_part + ((size_t)(b * CPB_ + jj) * 7) * N_ + t;
                #pragma unroll
                for (int k = 0; k < K_; k++) dot[k] += p[k * N_];
                xn += p[6 * N_];
            }

            int   a  = 0;
            float bd = (xn + sCn[0]) - 2.0f * dot[0];
            #pragma unroll
            for (int k = 1; k < K_; k++) {
                float e = (xn + sCn[k]) - 2.0f * dot[k];
                if (e < bd) { bd = e; a = k; }
            }
            if (t < K_) sCnt[t] = 0;
            __syncthreads();
            sAssign[t] = (unsigned char)a;
            atomicAdd(&sCnt[a], 1);
            __syncthreads();
            if (t < K_) {
                int cnt = sCnt[t];
                sInv[t] = (cnt > 0) ? (1.0f / (float)cnt) : 0.0f;
            }
            __syncthreads();
        }

        // ========== phase 3: scatter-mean of slice j (x[b] is L2-hot) ========
        {
            // per-lane packed one-hot masks for positions jj*32+l
            u64 m2[9][3];
            #pragma unroll
            for (int jj = 0; jj < 9; jj++) {
                int a = (int)sAssign[jj * 32 + l];
                #pragma unroll
                for (int p = 0; p < 3; p++)
                    m2[jj][p] = pack2((a == 2 * p) ? 1.0f : 0.0f,
                                      (a == 2 * p + 1) ? 1.0f : 0.0f);
            }
            const bool hi = (l >= 16);
            const int  lk = l & 15;
            const int  myk = lk + (hi ? 3 : 0);
            const float invSel = (lk < 3) ? sInv[myk] : 0.0f;

            const float* xb = x + (size_t)b * ((size_t)C_ * N_);

            // warp w handles columns c0 + w, w+9, w+18, ... (< CSL_)
            #pragma unroll 1
            for (int cl_ = w; cl_ < CSL_; cl_ += 9) {
                const int c = c0 + cl_;
                const float* row = xb + (size_t)c * N_;
                float v[9];
                #pragma unroll
                for (int jj = 0; jj < 9; jj++) v[jj] = row[jj * 32 + l];

                u64 s2[3];
                #pragma unroll
                for (int p = 0; p < 3; p++) s2[p] = 0ull;
                #pragma unroll
                for (int jj = 0; jj < 9; jj++) {
                    u64 vv = pack2(v[jj], v[jj]);
                    #pragma unroll
                    for (int p = 0; p < 3; p++) fma2(s2[p], m2[jj][p], vv);
                }

                float s[K_];
                unpack2(s2[0], s[0], s[1]);
                unpack2(s2[1], s[2], s[3]);
                unpack2(s2[2], s[4], s[5]);

                float r0 = hi ? s[3] : s[0];
                float r1 = hi ? s[4] : s[1];
                float r2 = hi ? s[5] : s[2];
                float o0 = hi ? s[0] : s[3];
                float o1 = hi ? s[1] : s[4];
                float o2 = hi ? s[2] : s[5];
                r0 += __shfl_xor_sync(0xffffffffu, o0, 16);
                r1 += __shfl_xor_sync(0xffffffffu, o1, 16);
                r2 += __shfl_xor_sync(0xffffffffu, o2, 16);
                #pragma unroll
                for (int o = 8; o; o >>= 1) {
                    r0 += __shfl_xor_sync(0xffffffffu, r0, o);
                    r1 += __shfl_xor_sync(0xffffffffu, r1, o);
                    r2 += __shfl_xor_sync(0xffffffffu, r2, o);
                }

                float res = r0;
                res = (lk == 1) ? r1 : res;
                res = (lk == 2) ? r2 : res;
                if (lk < 3) out[((size_t)b * C_ + c) * K_ + myk] = res * invSel;
            }
        }
        __syncthreads();   // protect sAssign/sInv before next batch reuses them
    }
}

extern "C" void kernel_launch(void* const* d_in, const int* in_sizes, int n_in,
                              void* d_out, int out_size) {
    const float* x  = (const float*)d_in[0];   // [256, 2048, 24, 12]
    const float* cl = (const float*)d_in[1];   // [6, 2048]
    float* out = (float*)d_out;                // [B, C, K]

    init_kernel<<<1, 256>>>();
    fused_kernel<<<GRID_, N_>>>(x, cl, out);
}

// round 14
// speedup vs baseline: 1.3059x; 1.3059x over previous
#include <cuda_runtime.h>

#define B_ 256
#define C_ 2048
#define N_ 288
#define K_ 6

typedef unsigned long long u64;

// scratch (no allocations allowed)
__device__ unsigned char g_assign[B_ * N_];
__device__ float g_inv[B_ * K_];
// partial dots: [512 half-blocks][7 (6 dots + xnorm)][288]
__device__ float g_part[(size_t)B_ * 2 * 7 * N_];

__device__ __forceinline__ u64 pack2(float lo, float hi) {
    u64 p;
    asm("mov.b64 %0, {%1, %2};" : "=l"(p) : "f"(lo), "f"(hi));
    return p;
}
__device__ __forceinline__ void unpack2(u64 p, float& lo, float& hi) {
    asm("mov.b64 {%0, %1}, %2;" : "=f"(lo), "=f"(hi) : "l"(p));
}
__device__ __forceinline__ float unpack_sum(u64 p) {
    float lo, hi;
    unpack2(p, lo, hi);
    return lo + hi;
}
__device__ __forceinline__ void fma2(u64& d, u64 a, u64 b) {
    asm("fma.rn.f32x2 %0, %1, %2, %3;" : "=l"(d) : "l"(a), "l"(b), "l"(d));
}

// ---------------------------------------------------------------------------
// Kernel A (R6, measured 112.4us @5.4TB/s): partial dots.
// grid = 2*B (CTA per (batch, C-half)), 288 threads (thread <-> n).
// b-major CTA order => at kernel end, L2 holds the last ~56 batches of x.
// ---------------------------------------------------------------------------
__global__ void __launch_bounds__(N_, 4) assign_part_kernel(const float* __restrict__ x,
                                                            const float* __restrict__ cl) {
    __shared__ float sCl[K_][1024];

    const int bx = blockIdx.x;
    const int b = bx >> 1;
    const int half = bx & 1;
    const int t = threadIdx.x;

    for (int i = t; i < K_ * 1024; i += N_) {
        int k = i >> 10, cc = i & 1023;
        sCl[k][cc] = cl[k * C_ + half * 1024 + cc];
    }
    __syncthreads();

    const float* xh = x + (size_t)b * ((size_t)C_ * N_) + (size_t)half * 1024 * N_ + t;

    u64 d2[K_];
    #pragma unroll
    for (int k = 0; k < K_; k++) d2[k] = 0ull;
    u64 xn2 = 0ull;

    float v[8], vn[8];
    #pragma unroll
    for (int u = 0; u < 8; u++) v[u] = xh[(size_t)u * N_];

    #pragma unroll 1
    for (int c = 0; c < 1024; c += 8) {
        if (c + 8 < 1024) {
            #pragma unroll
            for (int u = 0; u < 8; u++) vn[u] = xh[(size_t)(c + 8 + u) * N_];
        }
        u64 vp[4];
        #pragma unroll
        for (int u = 0; u < 4; u++) vp[u] = pack2(v[2 * u], v[2 * u + 1]);
        #pragma unroll
        for (int u = 0; u < 4; u++) fma2(xn2, vp[u], vp[u]);
        #pragma unroll
        for (int k = 0; k < K_; k++) {
            ulonglong2 q0 = *(const ulonglong2*)&sCl[k][c];
            ulonglong2 q1 = *(const ulonglong2*)&sCl[k][c + 4];
            fma2(d2[k], vp[0], q0.x);
            fma2(d2[k], vp[1], q0.y);
            fma2(d2[k], vp[2], q1.x);
            fma2(d2[k], vp[3], q1.y);
        }
        #pragma unroll
        for (int u = 0; u < 8; u++) v[u] = vn[u];
    }

    float* p = g_part + (size_t)bx * 7 * N_ + t;
    #pragma unroll
    for (int k = 0; k < K_; k++) p[k * N_] = unpack_sum(d2[k]);
    p[6 * N_] = unpack_sum(xn2);
}

// ---------------------------------------------------------------------------
// Kernel C: combine partials, argmin, counts. grid = B, 288 threads.
// ---------------------------------------------------------------------------
__global__ void __launch_bounds__(N_) argmin_kernel(const float* __restrict__ cl) {
    __shared__ float sCn[K_];
    __shared__ int   sCnt[K_];

    const int b = blockIdx.x;
    const int t = threadIdx.x;
    const int w = t >> 5;
    const int l = t & 31;

    if (t < K_) sCnt[t] = 0;

    if (w < K_) {
        float s = 0.f;
        for (int c = l; c < C_; c += 32) {
            float v = __ldg(&cl[w * C_ + c]);
            s = fmaf(v, v, s);
        }
        #pragma unroll
        for (int o = 16; o; o >>= 1) s += __shfl_xor_sync(0xffffffffu, s, o);
        if (l == 0) sCn[w] = s;
    }
    __syncthreads();

    const float* p0 = g_part + (size_t)(2 * b) * 7 * N_ + t;
    const float* p1 = g_part + (size_t)(2 * b + 1) * 7 * N_ + t;

    float xn = p0[6 * N_] + p1[6 * N_];
    int   a  = 0;
    float bd = (xn + sCn[0]) - 2.0f * (p0[0] + p1[0]);
    #pragma unroll
    for (int k = 1; k < K_; k++) {
        float e = (xn + sCn[k]) - 2.0f * (p0[k * N_] + p1[k * N_]);
        if (e < bd) { bd = e; a = k; }
    }
    g_assign[b * N_ + t] = (unsigned char)a;

    atomicAdd(&sCnt[a], 1);
    __syncthreads();
    if (t < K_) {
        int cnt = sCnt[t];
        g_inv[b * K_ + t] = (cnt > 0) ? (1.0f / (float)cnt) : 0.0f;
    }
}

// ---------------------------------------------------------------------------
// Kernel B: scatter-mean. grid = 16*B CTAs of 128 threads (4 warps).
// REVERSE-batch, b-major CTA order: first resident wave covers batches
// 255..~209 (all 16 q) — the x data still in L2 from the assign pass.
// 3-buffer rolling register prefetch (18 lines in flight per warp).
// Split-shuffle reduce (lanes<16 own k0..2, lanes>=16 own k3..5).
// ---------------------------------------------------------------------------
__global__ void __launch_bounds__(128, 4) sum_kernel(const float* __restrict__ x,
                                                     float* __restrict__ out) {
    const int b = 255 - (blockIdx.x >> 4);
    const int q = blockIdx.x & 15;
    const int w = threadIdx.x >> 5;
    const int l = threadIdx.x & 31;

    // packed one-hot masks for this lane's 9 positions (fixed per batch)
    u64 m2[9][3];
    #pragma unroll
    for (int j = 0; j < 9; j++) {
        int a = (int)g_assign[b * N_ + j * 32 + l];
        #pragma unroll
        for (int p = 0; p < 3; p++)
            m2[j][p] = pack2((a == 2 * p) ? 1.0f : 0.0f,
                             (a == 2 * p + 1) ? 1.0f : 0.0f);
    }

    const bool hi = (l >= 16);
    const int  lk = l & 15;
    const int  myk = lk + (hi ? 3 : 0);
    const float invSel = (lk < 3) ? g_inv[b * K_ + myk] : 0.0f;

    const int c0 = q * 128 + w * 32;
    // single strided pointer, advanced by one row (N_ floats) per iteration
    const float* rp = x + (size_t)b * ((size_t)C_ * N_) + (size_t)c0 * N_ + l;

    float v[9], w1[9], w2[9];
    #pragma unroll
    for (int j = 0; j < 9; j++) v[j]  = rp[j * 32];
    rp += N_;
    #pragma unroll
    for (int j = 0; j < 9; j++) w1[j] = rp[j * 32];
    rp += N_;

    #pragma unroll 1
    for (int i = 0; i < 32; i++) {
        if (i + 2 < 32) {
            #pragma unroll
            for (int j = 0; j < 9; j++) w2[j] = rp[j * 32];
        }
        rp += N_;

        u64 s2[3];
        #pragma unroll
        for (int p = 0; p < 3; p++) s2[p] = 0ull;
        #pragma unroll
        for (int j = 0; j < 9; j++) {
            u64 vv = pack2(v[j], v[j]);
            #pragma unroll
            for (int p = 0; p < 3; p++) fma2(s2[p], m2[j][p], vv);
        }

        float s[K_];
        unpack2(s2[0], s[0], s[1]);
        unpack2(s2[1], s[2], s[3]);
        unpack2(s2[2], s[4], s[5]);

        float r0 = hi ? s[3] : s[0];
        float r1 = hi ? s[4] : s[1];
        float r2 = hi ? s[5] : s[2];
        float o0 = hi ? s[0] : s[3];
        float o1 = hi ? s[1] : s[4];
        float o2 = hi ? s[2] : s[5];
        r0 += __shfl_xor_sync(0xffffffffu, o0, 16);
        r1 += __shfl_xor_sync(0xffffffffu, o1, 16);
        r2 += __shfl_xor_sync(0xffffffffu, o2, 16);
        #pragma unroll
        for (int o = 8; o; o >>= 1) {
            r0 += __shfl_xor_sync(0xffffffffu, r0, o);
            r1 += __shfl_xor_sync(0xffffffffu, r1, o);
            r2 += __shfl_xor_sync(0xffffffffu, r2, o);
        }

        float res = r0;
        res = (lk == 1) ? r1 : res;
        res = (lk == 2) ? r2 : res;
        if (lk < 3) out[((size_t)b * C_ + (c0 + i)) * K_ + myk] = res * invSel;

        #pragma unroll
        for (int j = 0; j < 9; j++) { v[j] = w1[j]; w1[j] = w2[j]; }
    }
}

extern "C" void kernel_launch(void* const* d_in, const int* in_sizes, int n_in,
                              void* d_out, int out_size) {
    const float* x  = (const float*)d_in[0];   // [256, 2048, 24, 12]
    const float* cl = (const float*)d_in[1];   // [6, 2048]
    float* out = (float*)d_out;                // [B, C, K]

    assign_part_kernel<<<B_ * 2, N_>>>(x, cl);
    argmin_kernel<<<B_, N_>>>(cl);
    sum_kernel<<<B_ * 16, 128>>>(x, out);
}